// round 5
// baseline (speedup 1.0000x reference)
#include <cuda_runtime.h>
#include <cuda_fp16.h>
#include <cstdint>
#include <cstddef>

#define DEV __device__ __forceinline__

static constexpr int Bn = 8192;   // batch rows
static constexpr int Dd = 2048;   // model dim (K of GEMMs, N of V GEMM)
static constexpr int Ff = 1024;   // feature dim (N of Q/K GEMMs)

// ---------------- scratch (device globals: allocation-free) ----------------
__device__ __half g_WqT[(size_t)Ff * Dd];   // [F][D] 4 MB
__device__ __half g_WkT[(size_t)Ff * Dd];   // [F][D] 4 MB
__device__ __half g_WvT[(size_t)Dd * Dd];   // [D][D] 8 MB
__device__ float g_sQ[Bn];
__device__ float g_sK[Bn];
__device__ float g_qk[Bn];

// ---------------- helpers ----------------
DEV uint32_t smem_u32(const void* p) {
  uint32_t a;
  asm("{ .reg .u64 t; cvta.to.shared.u64 t, %1; cvt.u32.u64 %0, t; }" : "=r"(a) : "l"(p));
  return a;
}
DEV void cp16(uint32_t dst, const void* src) {
  asm volatile("cp.async.cg.shared.global [%0], [%1], 16;" :: "r"(dst), "l"(src));
}
DEV void cp_commit() { asm volatile("cp.async.commit_group;" ::: "memory"); }
DEV void cp_wait1()  { asm volatile("cp.async.wait_group 1;" ::: "memory"); }
DEV void cp_wait2()  { asm volatile("cp.async.wait_group 2;" ::: "memory"); }

// mma m16n8k16 fp16 (fp32 acc): A row-major (4 regs = 8 halves), B col-major (2 regs)
DEV void mma16(float c[4], const uint32_t a[4], const uint32_t b[2]) {
  asm volatile(
    "mma.sync.aligned.m16n8k16.row.col.f32.f16.f16.f32 "
    "{%0,%1,%2,%3}, {%4,%5,%6,%7}, {%8,%9}, {%0,%1,%2,%3};"
    : "+f"(c[0]), "+f"(c[1]), "+f"(c[2]), "+f"(c[3])
    : "r"(a[0]), "r"(a[1]), "r"(a[2]), "r"(a[3]), "r"(b[0]), "r"(b[1]));
}

DEV float elu_f(float x) { return x > 0.f ? x : expm1f(x); }
DEV uint32_t ldh2(const __half* p) { return *reinterpret_cast<const uint32_t*>(p); }
DEV uint32_t f2h2(float2 v) {               // pack two fp32 -> half2 (lo = .x)
  __half2 h = __floats2half2_rn(v.x, v.y);
  return *reinterpret_cast<uint32_t*>(&h);
}

// A (fp32) smem rows: 32 floats (128 B) padded to 36 floats (144 B = 9*16 B).
// B (fp16) smem rows: 32 halves (64 B) padded to 40 halves (80 B = 5*16 B);
// word bank = (20r + tig) mod 32: distinct across the warp for B-frag loads.
static constexpr int AROWF = 36;                   // floats per padded A row
static constexpr int AROWB = 144;
static constexpr int BROWH = 40;                   // halves per padded B row
static constexpr int BROWB = 80;

// ---------------- prep kernels ----------------
__global__ void transpose_qk_kernel(const float* __restrict__ Wq,
                                    const float* __restrict__ Wk) {
  // src[2048][1024] fp32 -> dst[1024][2048] fp16; z selects Wq/Wk
  __shared__ float tile[32][33];
  const float* src = (blockIdx.z == 0) ? Wq : Wk;
  __half* dst = (blockIdx.z == 0) ? g_WqT : g_WkT;
  const int c0 = blockIdx.x * 32, r0 = blockIdx.y * 32;
  const int tx = threadIdx.x, ty = threadIdx.y;
  #pragma unroll
  for (int i = 0; i < 32; i += 8)
    tile[ty + i][tx] = src[(size_t)(r0 + ty + i) * Ff + (c0 + tx)];
  __syncthreads();
  #pragma unroll
  for (int i = 0; i < 32; i += 8)
    dst[(size_t)(c0 + ty + i) * Dd + (r0 + tx)] = __float2half_rn(tile[tx][ty + i]);
}

__global__ void transpose_v_kernel(const float* __restrict__ Wv) {
  __shared__ float tile[32][33];
  const int c0 = blockIdx.x * 32, r0 = blockIdx.y * 32;
  const int tx = threadIdx.x, ty = threadIdx.y;
  #pragma unroll
  for (int i = 0; i < 32; i += 8)
    tile[ty + i][tx] = Wv[(size_t)(r0 + ty + i) * Dd + (c0 + tx)];
  __syncthreads();
  #pragma unroll
  for (int i = 0; i < 32; i += 8)
    g_WvT[(size_t)(c0 + ty + i) * Dd + (r0 + tx)] = __float2half_rn(tile[tx][ty + i]);
}

__global__ void zero_kernel() {
  int i = blockIdx.x * blockDim.x + threadIdx.x;
  if (i < Bn) { g_sQ[i] = 0.f; g_sK[i] = 0.f; g_qk[i] = 0.f; }
}

// ---------------- fused Q/K feature kernel ----------------
// CTA 64 rows x 128 feature cols, BOTH gemms; 8 warps (wm 2 x wn 4),
// warp tile 32x32 per gemm. K-chunk 32, 2-stage cp.async, 2 CTAs/SM.
// Stage: A region fp32 128 rows (Q 64 | K 64) = 18432 B, then
// B region fp16 256 rows (BQ 128 | BK 128) = 20480 B. Stage = 38912 B.
static constexpr int QK_AREG  = 128 * AROWB;              // 18432
static constexpr int QK_STAGE = QK_AREG + 256 * BROWB;    // 38912
static constexpr int QK_SMEM  = 2 * QK_STAGE;             // 77824

__global__ void __launch_bounds__(256, 2)
gemm_qk_kernel(const float* __restrict__ Q, const float* __restrict__ Kin,
               const float* __restrict__ bq, const float* __restrict__ bk)
{
  extern __shared__ __align__(128) char smem[];
  const uint32_t sb = smem_u32(smem);
  const int tid = threadIdx.x;
  const int wid = tid >> 5, lane = tid & 31;
  const int g = lane >> 2, tig = lane & 3;
  const int wm = wid >> 2, wn = wid & 3;
  const int m0 = blockIdx.y * 64;
  const int n0 = blockIdx.x * 128;

  auto load_stage = [&](int it, int s) {
    const int k0 = it * 32;
    const uint32_t base = sb + (uint32_t)s * QK_STAGE;
    // A region fp32: 1024 16B chunks (rows 0-63 Q, 64-127 K); 4 per thread.
    #pragma unroll
    for (int i = 0; i < 4; ++i) {
      int ch = tid + i * 256;               // i<2 -> Q, i>=2 -> K (uniform)
      int r = ch >> 3, c = ch & 7;
      uint32_t off = (uint32_t)(r * AROWB + c * 16);
      const float* src = (i < 2) ? (Q   + (size_t)(m0 + r) * Dd)
                                 : (Kin + (size_t)(m0 + r - 64) * Dd);
      cp16(base + off, src + k0 + c * 4);
    }
    // B region fp16: 1024 chunks (rows 0-127 Wq, 128-255 Wk); 4 per thread.
    #pragma unroll
    for (int i = 0; i < 4; ++i) {
      int ch = tid + i * 256;               // i<2 -> BQ, i>=2 -> BK (uniform)
      int r = ch >> 2, c = ch & 3;
      uint32_t off = (uint32_t)(QK_AREG + r * BROWB + c * 16);
      const __half* src = (i < 2) ? (g_WqT + (size_t)(n0 + r) * Dd)
                                  : (g_WkT + (size_t)(n0 + r - 128) * Dd);
      cp16(base + off, src + k0 + c * 8);
    }
    cp_commit();
  };

  float cQ[2][4][4], cK[2][4][4];
  #pragma unroll
  for (int i = 0; i < 2; ++i)
    #pragma unroll
    for (int j = 0; j < 4; ++j)
      #pragma unroll
      for (int t = 0; t < 4; ++t) { cQ[i][j][t] = 0.f; cK[i][j][t] = 0.f; }

  load_stage(0, 0);

  const int NIT = Dd / 32;   // 64
  for (int it = 0; it < NIT; ++it) {
    __syncthreads();
    if (it + 1 < NIT) load_stage(it + 1, (it + 1) & 1);
    else cp_commit();
    cp_wait1();
    __syncthreads();

    const char* stg = smem + (size_t)(it & 1) * QK_STAGE;
    const float* AQs = reinterpret_cast<const float*>(stg);
    const float* AKs = AQs + 64 * AROWF;
    const __half* BQs = reinterpret_cast<const __half*>(stg + QK_AREG);
    const __half* BKs = BQs + 128 * BROWH;

    #pragma unroll
    for (int ks = 0; ks < 2; ++ks) {
      const int kc = ks * 16;
      uint32_t aQ[2][4], aK[2][4];
      #pragma unroll
      for (int i = 0; i < 2; ++i) {
        const int r = wm * 32 + i * 16 + g;
        aQ[i][0] = f2h2(*reinterpret_cast<const float2*>(AQs + (r    ) * AROWF + kc + 2 * tig));
        aQ[i][1] = f2h2(*reinterpret_cast<const float2*>(AQs + (r + 8) * AROWF + kc + 2 * tig));
        aQ[i][2] = f2h2(*reinterpret_cast<const float2*>(AQs + (r    ) * AROWF + kc + 2 * tig + 8));
        aQ[i][3] = f2h2(*reinterpret_cast<const float2*>(AQs + (r + 8) * AROWF + kc + 2 * tig + 8));
        aK[i][0] = f2h2(*reinterpret_cast<const float2*>(AKs + (r    ) * AROWF + kc + 2 * tig));
        aK[i][1] = f2h2(*reinterpret_cast<const float2*>(AKs + (r + 8) * AROWF + kc + 2 * tig));
        aK[i][2] = f2h2(*reinterpret_cast<const float2*>(AKs + (r    ) * AROWF + kc + 2 * tig + 8));
        aK[i][3] = f2h2(*reinterpret_cast<const float2*>(AKs + (r + 8) * AROWF + kc + 2 * tig + 8));
      }
      uint32_t bQ[4][2], bK[4][2];
      #pragma unroll
      for (int j = 0; j < 4; ++j) {
        const int n = wn * 32 + j * 8 + g;
        bQ[j][0] = ldh2(BQs + n * BROWH + kc + 2 * tig);
        bQ[j][1] = ldh2(BQs + n * BROWH + kc + 2 * tig + 8);
        bK[j][0] = ldh2(BKs + n * BROWH + kc + 2 * tig);
        bK[j][1] = ldh2(BKs + n * BROWH + kc + 2 * tig + 8);
      }
      #pragma unroll
      for (int i = 0; i < 2; ++i)
        #pragma unroll
        for (int j = 0; j < 4; ++j) {
          mma16(cQ[i][j], aQ[i], bQ[j]);
          mma16(cK[i][j], aK[i], bK[j]);
        }
    }
  }

  // Epilogue: bias + ELU + per-row reductions (sum Q, sum K, sum Q*K)
  float bqc[4][2], bkc[4][2];
  #pragma unroll
  for (int j = 0; j < 4; ++j) {
    const int col = n0 + wn * 32 + j * 8 + 2 * tig;
    bqc[j][0] = bq[col]; bqc[j][1] = bq[col + 1];
    bkc[j][0] = bk[col]; bkc[j][1] = bk[col + 1];
  }
  #pragma unroll
  for (int i = 0; i < 2; ++i) {
    const int r0 = m0 + wm * 32 + i * 16 + g;
    const int r1 = r0 + 8;
    float s0q = 0.f, s0k = 0.f, p0 = 0.f, s1q = 0.f, s1k = 0.f, p1 = 0.f;
    #pragma unroll
    for (int j = 0; j < 4; ++j) {
      float q00 = elu_f(cQ[i][j][0] + bqc[j][0]);
      float q01 = elu_f(cQ[i][j][1] + bqc[j][1]);
      float q10 = elu_f(cQ[i][j][2] + bqc[j][0]);
      float q11 = elu_f(cQ[i][j][3] + bqc[j][1]);
      float k00 = elu_f(cK[i][j][0] + bkc[j][0]);
      float k01 = elu_f(cK[i][j][1] + bkc[j][1]);
      float k10 = elu_f(cK[i][j][2] + bkc[j][0]);
      float k11 = elu_f(cK[i][j][3] + bkc[j][1]);
      s0q += q00 + q01; s0k += k00 + k01; p0 += q00 * k00 + q01 * k01;
      s1q += q10 + q11; s1k += k10 + k11; p1 += q10 * k10 + q11 * k11;
    }
    #pragma unroll
    for (int m = 1; m <= 2; m <<= 1) {
      s0q += __shfl_xor_sync(0xffffffffu, s0q, m);
      s0k += __shfl_xor_sync(0xffffffffu, s0k, m);
      p0  += __shfl_xor_sync(0xffffffffu, p0,  m);
      s1q += __shfl_xor_sync(0xffffffffu, s1q, m);
      s1k += __shfl_xor_sync(0xffffffffu, s1k, m);
      p1  += __shfl_xor_sync(0xffffffffu, p1,  m);
    }
    if (tig == 0) {
      atomicAdd(&g_sQ[r0], s0q); atomicAdd(&g_sK[r0], s0k); atomicAdd(&g_qk[r0], p0);
      atomicAdd(&g_sQ[r1], s1q); atomicAdd(&g_sK[r1], s1k); atomicAdd(&g_qk[r1], p1);
    }
  }
}

// ---------------- V projection kernel ----------------
// CTA 128x128, K-chunk 32, 3-stage pipeline, 2 CTAs/SM.
// Stage: A fp32 128 rows = 18432 B, B fp16 128 rows = 10240 B -> 28672 B.
static constexpr int V_AREG  = 128 * AROWB;               // 18432
static constexpr int V_STAGE = V_AREG + 128 * BROWB;      // 28672
static constexpr int V_SMEM  = 3 * V_STAGE;               // 86016

__global__ void __launch_bounds__(256, 2)
gemm_v_kernel(const float* __restrict__ V, const float* __restrict__ bv,
              float* __restrict__ out)
{
  extern __shared__ __align__(128) char smem[];
  const uint32_t sb = smem_u32(smem);
  const int tid = threadIdx.x;
  const int wid = tid >> 5, lane = tid & 31;
  const int g = lane >> 2, tig = lane & 3;
  const int wm = wid >> 2, wn = wid & 3;
  const int m0 = blockIdx.y * 128;
  const int n0 = blockIdx.x * 128;

  auto load_stage = [&](int it, int s) {
    const int k0 = it * 32;
    const uint32_t base = sb + (uint32_t)s * V_STAGE;
    // A fp32: 1024 chunks, 4 per thread
    #pragma unroll
    for (int i = 0; i < 4; ++i) {
      int ch = tid + i * 256;
      int r = ch >> 3, c = ch & 7;
      uint32_t off = (uint32_t)(r * AROWB + c * 16);
      cp16(base + off, V + (size_t)(m0 + r) * Dd + k0 + c * 4);
    }
    // B fp16: 512 chunks, 2 per thread
    #pragma unroll
    for (int i = 0; i < 2; ++i) {
      int ch = tid + i * 256;
      int r = ch >> 2, c = ch & 3;
      uint32_t off = (uint32_t)(V_AREG + r * BROWB + c * 16);
      cp16(base + off, g_WvT + (size_t)(n0 + r) * Dd + k0 + c * 8);
    }
    cp_commit();
  };

  float cc[4][4][4];
  #pragma unroll
  for (int i = 0; i < 4; ++i)
    #pragma unroll
    for (int j = 0; j < 4; ++j)
      #pragma unroll
      for (int t = 0; t < 4; ++t) cc[i][j][t] = 0.f;

  load_stage(0, 0);
  load_stage(1, 1);

  const int NIT = Dd / 32;   // 64
  for (int it = 0; it < NIT; ++it) {
    __syncthreads();
    if (it + 2 < NIT) load_stage(it + 2, (it + 2) % 3);
    else cp_commit();
    cp_wait2();
    __syncthreads();

    const char* stg = smem + (size_t)(it % 3) * V_STAGE;
    const float* As = reinterpret_cast<const float*>(stg);
    const __half* Bs = reinterpret_cast<const __half*>(stg + V_AREG);

    #pragma unroll
    for (int ks = 0; ks < 2; ++ks) {
      const int kc = ks * 16;
      uint32_t a[4][4];
      #pragma unroll
      for (int i = 0; i < 4; ++i) {
        const int r = wm * 64 + i * 16 + g;
        a[i][0] = f2h2(*reinterpret_cast<const float2*>(As + (r    ) * AROWF + kc + 2 * tig));
        a[i][1] = f2h2(*reinterpret_cast<const float2*>(As + (r + 8) * AROWF + kc + 2 * tig));
        a[i][2] = f2h2(*reinterpret_cast<const float2*>(As + (r    ) * AROWF + kc + 2 * tig + 8));
        a[i][3] = f2h2(*reinterpret_cast<const float2*>(As + (r + 8) * AROWF + kc + 2 * tig + 8));
      }
      uint32_t b[4][2];
      #pragma unroll
      for (int j = 0; j < 4; ++j) {
        const int n = wn * 32 + j * 8 + g;
        b[j][0] = ldh2(Bs + n * BROWH + kc + 2 * tig);
        b[j][1] = ldh2(Bs + n * BROWH + kc + 2 * tig + 8);
      }
      #pragma unroll
      for (int i = 0; i < 4; ++i)
        #pragma unroll
        for (int j = 0; j < 4; ++j)
          mma16(cc[i][j], a[i], b[j]);
    }
  }

  // Epilogue: out[r, n] = coef[r] * (acc + bv[n])
  float bvc[4][2];
  #pragma unroll
  for (int j = 0; j < 4; ++j) {
    const int col = n0 + wn * 32 + j * 8 + 2 * tig;
    bvc[j][0] = bv[col]; bvc[j][1] = bv[col + 1];
  }
  #pragma unroll
  for (int i = 0; i < 4; ++i) {
    const int r0 = m0 + wm * 64 + i * 16 + g;
    const int r1 = r0 + 8;
    const float c0 = g_qk[r0] / (g_sQ[r0] * g_sK[r0] + 1e-6f);
    const float c1 = g_qk[r1] / (g_sQ[r1] * g_sK[r1] + 1e-6f);
    #pragma unroll
    for (int j = 0; j < 4; ++j) {
      const int col = n0 + wn * 32 + j * 8 + 2 * tig;
      float2 v0, v1;
      v0.x = c0 * (cc[i][j][0] + bvc[j][0]);
      v0.y = c0 * (cc[i][j][1] + bvc[j][1]);
      v1.x = c1 * (cc[i][j][2] + bvc[j][0]);
      v1.y = c1 * (cc[i][j][3] + bvc[j][1]);
      *reinterpret_cast<float2*>(out + (size_t)r0 * Dd + col) = v0;
      *reinterpret_cast<float2*>(out + (size_t)r1 * Dd + col) = v1;
    }
  }
}

// ---------------- host launcher ----------------
extern "C" void kernel_launch(void* const* d_in, const int* /*in_sizes*/, int /*n_in*/,
                              void* d_out, int /*out_size*/) {
  const float* Q  = (const float*)d_in[0];
  const float* K  = (const float*)d_in[1];
  const float* V  = (const float*)d_in[2];
  const float* Wq = (const float*)d_in[3];
  const float* bq = (const float*)d_in[4];
  const float* Wk = (const float*)d_in[5];
  const float* bk = (const float*)d_in[6];
  const float* Wv = (const float*)d_in[7];
  const float* bv = (const float*)d_in[8];
  float* out = (float*)d_out;

  cudaFuncSetAttribute(gemm_qk_kernel, cudaFuncAttributeMaxDynamicSharedMemorySize, QK_SMEM);
  cudaFuncSetAttribute(gemm_v_kernel,  cudaFuncAttributeMaxDynamicSharedMemorySize, V_SMEM);

  // launch index 3 is the one ncu profiles -> put gemm_qk there
  transpose_qk_kernel<<<dim3(Ff / 32, Dd / 32, 2), dim3(32, 8)>>>(Wq, Wk);   // 0
  transpose_v_kernel <<<dim3(Dd / 32, Dd / 32),    dim3(32, 8)>>>(Wv);        // 1
  zero_kernel<<<Bn / 256, 256>>>();                                           // 2
  gemm_qk_kernel<<<dim3(Ff / 128, Bn / 64), 256, QK_SMEM>>>(Q, K, bq, bk);    // 3
  gemm_v_kernel <<<dim3(Dd / 128, Bn / 128), 256, V_SMEM>>>(V, bv, out);      // 4
}

// round 6
// speedup vs baseline: 1.4574x; 1.4574x over previous
#include <cuda_runtime.h>
#include <cuda_fp16.h>
#include <cstdint>
#include <cstddef>

#define DEV __device__ __forceinline__

static constexpr int Bn = 8192;   // batch rows
static constexpr int Dd = 2048;   // model dim (K of GEMMs, N of V GEMM)
static constexpr int Ff = 1024;   // feature dim (N of Q/K GEMMs)

// ---------------- scratch (device globals: allocation-free) ----------------
__device__ __half g_WqT[(size_t)Ff * Dd];   // [F][D] 4 MB
__device__ __half g_WkT[(size_t)Ff * Dd];   // [F][D] 4 MB
__device__ __half g_WvT[(size_t)Dd * Dd];   // [D][D] 8 MB
__device__ float g_sQ[Bn];
__device__ float g_sK[Bn];
__device__ float g_qk[Bn];

// ---------------- helpers ----------------
DEV uint32_t smem_u32(const void* p) {
  uint32_t a;
  asm("{ .reg .u64 t; cvta.to.shared.u64 t, %1; cvt.u32.u64 %0, t; }" : "=r"(a) : "l"(p));
  return a;
}
DEV void cp16(uint32_t dst, const void* src) {
  asm volatile("cp.async.cg.shared.global [%0], [%1], 16;" :: "r"(dst), "l"(src));
}
DEV void cp_commit() { asm volatile("cp.async.commit_group;" ::: "memory"); }
DEV void cp_wait1()  { asm volatile("cp.async.wait_group 1;" ::: "memory"); }

// mma m16n8k16 fp16 (fp32 acc)
DEV void mma16(float c[4], const uint32_t a[4], const uint32_t b[2]) {
  asm volatile(
    "mma.sync.aligned.m16n8k16.row.col.f32.f16.f16.f32 "
    "{%0,%1,%2,%3}, {%4,%5,%6,%7}, {%8,%9}, {%0,%1,%2,%3};"
    : "+f"(c[0]), "+f"(c[1]), "+f"(c[2]), "+f"(c[3])
    : "r"(a[0]), "r"(a[1]), "r"(a[2]), "r"(a[3]), "r"(b[0]), "r"(b[1]));
}

DEV float elu_f(float x) { return x > 0.f ? x : expm1f(x); }
DEV uint32_t ldh2(const __half* p) { return *reinterpret_cast<const uint32_t*>(p); }
DEV uint32_t f2h2(float x, float y) {
  __half2 h = __floats2half2_rn(x, y);
  return *reinterpret_cast<uint32_t*>(&h);
}
DEV void sts64(uint32_t addr, uint32_t lo, uint32_t hi) {
  asm volatile("st.shared.v2.b32 [%0], {%1, %2};" :: "r"(addr), "r"(lo), "r"(hi));
}

// All smem tiles fp16: rows of 32 halves (64 B) padded to 40 halves (80 B).
// Fragment word-bank = (20*row + tig) mod 32 -> distinct across the warp for
// both A-frag (rows 16i+g/+8) and B-frag (rows 8j+g) patterns: conflict-free.
static constexpr int ROWH = 40;   // halves per padded row
static constexpr int ROWB = 80;   // bytes per padded row

// ---------------- prep kernels ----------------
__global__ void transpose_qk_kernel(const float* __restrict__ Wq,
                                    const float* __restrict__ Wk) {
  __shared__ float tile[32][33];
  const float* src = (blockIdx.z == 0) ? Wq : Wk;
  __half* dst = (blockIdx.z == 0) ? g_WqT : g_WkT;
  const int c0 = blockIdx.x * 32, r0 = blockIdx.y * 32;
  const int tx = threadIdx.x, ty = threadIdx.y;
  #pragma unroll
  for (int i = 0; i < 32; i += 8)
    tile[ty + i][tx] = src[(size_t)(r0 + ty + i) * Ff + (c0 + tx)];
  __syncthreads();
  #pragma unroll
  for (int i = 0; i < 32; i += 8)
    dst[(size_t)(c0 + ty + i) * Dd + (r0 + tx)] = __float2half_rn(tile[tx][ty + i]);
}

__global__ void transpose_v_kernel(const float* __restrict__ Wv) {
  __shared__ float tile[32][33];
  const int c0 = blockIdx.x * 32, r0 = blockIdx.y * 32;
  const int tx = threadIdx.x, ty = threadIdx.y;
  #pragma unroll
  for (int i = 0; i < 32; i += 8)
    tile[ty + i][tx] = Wv[(size_t)(r0 + ty + i) * Dd + (c0 + tx)];
  __syncthreads();
  #pragma unroll
  for (int i = 0; i < 32; i += 8)
    g_WvT[(size_t)(c0 + ty + i) * Dd + (r0 + tx)] = __float2half_rn(tile[tx][ty + i]);
}

__global__ void zero_kernel() {
  int i = blockIdx.x * blockDim.x + threadIdx.x;
  if (i < Bn) { g_sQ[i] = 0.f; g_sK[i] = 0.f; g_qk[i] = 0.f; }
}

// ---------------- fused Q/K feature kernel ----------------
// CTA 64 rows x 128 cols, BOTH gemms; 8 warps (wm 2 x wn 4), warp 32x32/gemm.
// K-chunk 32. A tiles: fp32 LDG -> cvt -> fp16 STS (reg double-buffered);
// B tiles: cp.async from fp16 transposed weights. 2 stages, 2 CTAs/SM.
// Stage: A region 128 rows (Q 64 | K 64) = 10240 B; B region 256 rows = 20480 B.
static constexpr int QK_AREG  = 128 * ROWB;               // 10240
static constexpr int QK_STAGE = QK_AREG + 256 * ROWB;     // 30720
static constexpr int QK_SMEM  = 2 * QK_STAGE;             // 61440

__global__ void __launch_bounds__(256, 2)
gemm_qk_kernel(const float* __restrict__ Q, const float* __restrict__ Kin,
               const float* __restrict__ bq, const float* __restrict__ bk)
{
  extern __shared__ __align__(16) char smem[];
  const uint32_t sb = smem_u32(smem);
  const int tid = threadIdx.x;
  const int wid = tid >> 5, lane = tid & 31;
  const int g = lane >> 2, tig = lane & 3;
  const int wm = wid >> 2, wn = wid & 3;
  const int m0 = blockIdx.y * 64;
  const int n0 = blockIdx.x * 128;

  // Per-thread A-chunk geometry (fixed row/col, k0 varies).
  // chunk ch = tid + i*256; r = ch>>3 (0..127), c = ch&7 (4 floats each).
  const float* apx[4];
  uint32_t asts[4];
  #pragma unroll
  for (int i = 0; i < 4; ++i) {
    int ch = tid + i * 256;
    int r = ch >> 3, c = ch & 7;
    const float* base = (i < 2) ? (Q + (size_t)(m0 + r) * Dd)
                                : (Kin + (size_t)(m0 + r - 64) * Dd);
    apx[i]  = base + c * 4;
    asts[i] = (uint32_t)(r * ROWB + c * 8);
  }

  auto lda = [&](int it, float4 pf[4]) {
    const int k0 = it * 32;
    #pragma unroll
    for (int i = 0; i < 4; ++i)
      pf[i] = *reinterpret_cast<const float4*>(apx[i] + k0);
  };
  auto sta = [&](const float4 pf[4], int s) {
    const uint32_t base = sb + (uint32_t)s * QK_STAGE;
    #pragma unroll
    for (int i = 0; i < 4; ++i)
      sts64(base + asts[i], f2h2(pf[i].x, pf[i].y), f2h2(pf[i].z, pf[i].w));
  };
  auto ldb = [&](int it, int s) {
    const int k0 = it * 32;
    const uint32_t base = sb + (uint32_t)s * QK_STAGE + QK_AREG;
    #pragma unroll
    for (int i = 0; i < 4; ++i) {
      int ch = tid + i * 256;                 // 1024 chunks: BQ rows 0-127, BK 128-255
      int r = ch >> 2, c = ch & 3;
      uint32_t off = (uint32_t)(r * ROWB + c * 16);
      const __half* src = (i < 2) ? (g_WqT + (size_t)(n0 + r) * Dd)
                                  : (g_WkT + (size_t)(n0 + r - 128) * Dd);
      cp16(base + off, src + k0 + c * 8);
    }
    cp_commit();
  };

  float cQ[2][4][4], cK[2][4][4];
  #pragma unroll
  for (int i = 0; i < 2; ++i)
    #pragma unroll
    for (int j = 0; j < 4; ++j)
      #pragma unroll
      for (int t = 0; t < 4; ++t) { cQ[i][j][t] = 0.f; cK[i][j][t] = 0.f; }

  const int NIT = Dd / 32;   // 64
  float4 pf[4];
  lda(0, pf);
  sta(pf, 0);
  ldb(0, 0);
  lda(1, pf);

  for (int it = 0; it < NIT; ++it) {
    const int s = it & 1;
    if (it + 1 < NIT) {
      sta(pf, s ^ 1);          // A(it+1) -> other stage (safe: sync at loop end)
      ldb(it + 1, s ^ 1);
    } else cp_commit();
    cp_wait1();                // B(it) arrived
    __syncthreads();           // stage s fully populated for everyone
    if (it + 2 < NIT) lda(it + 2, pf);   // hidden under compute

    const __half* AQs = reinterpret_cast<const __half*>(smem + (size_t)s * QK_STAGE);
    const __half* AKs = AQs + 64 * ROWH;
    const __half* BQs = AQs + 128 * ROWH;      // = QK_AREG in halves
    const __half* BKs = BQs + 128 * ROWH;

    #pragma unroll
    for (int ks = 0; ks < 2; ++ks) {
      const int kc = ks * 16;
      uint32_t aQ[2][4], aK[2][4];
      #pragma unroll
      for (int i = 0; i < 2; ++i) {
        const int r = wm * 32 + i * 16 + g;
        aQ[i][0] = ldh2(AQs + (r    ) * ROWH + kc + 2 * tig);
        aQ[i][1] = ldh2(AQs + (r + 8) * ROWH + kc + 2 * tig);
        aQ[i][2] = ldh2(AQs + (r    ) * ROWH + kc + 2 * tig + 8);
        aQ[i][3] = ldh2(AQs + (r + 8) * ROWH + kc + 2 * tig + 8);
        aK[i][0] = ldh2(AKs + (r    ) * ROWH + kc + 2 * tig);
        aK[i][1] = ldh2(AKs + (r + 8) * ROWH + kc + 2 * tig);
        aK[i][2] = ldh2(AKs + (r    ) * ROWH + kc + 2 * tig + 8);
        aK[i][3] = ldh2(AKs + (r + 8) * ROWH + kc + 2 * tig + 8);
      }
      uint32_t bQ[4][2], bK[4][2];
      #pragma unroll
      for (int j = 0; j < 4; ++j) {
        const int n = wn * 32 + j * 8 + g;
        bQ[j][0] = ldh2(BQs + n * ROWH + kc + 2 * tig);
        bQ[j][1] = ldh2(BQs + n * ROWH + kc + 2 * tig + 8);
        bK[j][0] = ldh2(BKs + n * ROWH + kc + 2 * tig);
        bK[j][1] = ldh2(BKs + n * ROWH + kc + 2 * tig + 8);
      }
      #pragma unroll
      for (int i = 0; i < 2; ++i)
        #pragma unroll
        for (int j = 0; j < 4; ++j) {
          mma16(cQ[i][j], aQ[i], bQ[j]);
          mma16(cK[i][j], aK[i], bK[j]);
        }
    }
    __syncthreads();           // all reads of stage s done before it+1 STS into it
  }

  // Epilogue: bias + ELU + per-row reductions (sum Q, sum K, sum Q*K)
  float bqc[4][2], bkc[4][2];
  #pragma unroll
  for (int j = 0; j < 4; ++j) {
    const int col = n0 + wn * 32 + j * 8 + 2 * tig;
    bqc[j][0] = bq[col]; bqc[j][1] = bq[col + 1];
    bkc[j][0] = bk[col]; bkc[j][1] = bk[col + 1];
  }
  #pragma unroll
  for (int i = 0; i < 2; ++i) {
    const int r0 = m0 + wm * 32 + i * 16 + g;
    const int r1 = r0 + 8;
    float s0q = 0.f, s0k = 0.f, p0 = 0.f, s1q = 0.f, s1k = 0.f, p1 = 0.f;
    #pragma unroll
    for (int j = 0; j < 4; ++j) {
      float q00 = elu_f(cQ[i][j][0] + bqc[j][0]);
      float q01 = elu_f(cQ[i][j][1] + bqc[j][1]);
      float q10 = elu_f(cQ[i][j][2] + bqc[j][0]);
      float q11 = elu_f(cQ[i][j][3] + bqc[j][1]);
      float k00 = elu_f(cK[i][j][0] + bkc[j][0]);
      float k01 = elu_f(cK[i][j][1] + bkc[j][1]);
      float k10 = elu_f(cK[i][j][2] + bkc[j][0]);
      float k11 = elu_f(cK[i][j][3] + bkc[j][1]);
      s0q += q00 + q01; s0k += k00 + k01; p0 += q00 * k00 + q01 * k01;
      s1q += q10 + q11; s1k += k10 + k11; p1 += q10 * k10 + q11 * k11;
    }
    #pragma unroll
    for (int m = 1; m <= 2; m <<= 1) {
      s0q += __shfl_xor_sync(0xffffffffu, s0q, m);
      s0k += __shfl_xor_sync(0xffffffffu, s0k, m);
      p0  += __shfl_xor_sync(0xffffffffu, p0,  m);
      s1q += __shfl_xor_sync(0xffffffffu, s1q, m);
      s1k += __shfl_xor_sync(0xffffffffu, s1k, m);
      p1  += __shfl_xor_sync(0xffffffffu, p1,  m);
    }
    if (tig == 0) {
      atomicAdd(&g_sQ[r0], s0q); atomicAdd(&g_sK[r0], s0k); atomicAdd(&g_qk[r0], p0);
      atomicAdd(&g_sQ[r1], s1q); atomicAdd(&g_sK[r1], s1k); atomicAdd(&g_qk[r1], p1);
    }
  }
}

// ---------------- V projection kernel ----------------
// CTA 128x128, K-chunk 32, same LDG->STS A scheme, 2 stages, 2 CTAs/SM.
static constexpr int V_AREG  = 128 * ROWB;                // 10240
static constexpr int V_STAGE = V_AREG + 128 * ROWB;       // 20480
static constexpr int V_SMEM  = 2 * V_STAGE;               // 40960

__global__ void __launch_bounds__(256, 2)
gemm_v_kernel(const float* __restrict__ V, const float* __restrict__ bv,
              float* __restrict__ out)
{
  extern __shared__ __align__(16) char smem[];
  const uint32_t sb = smem_u32(smem);
  const int tid = threadIdx.x;
  const int wid = tid >> 5, lane = tid & 31;
  const int g = lane >> 2, tig = lane & 3;
  const int wm = wid >> 2, wn = wid & 3;
  const int m0 = blockIdx.y * 128;
  const int n0 = blockIdx.x * 128;

  const float* apx[4];
  uint32_t asts[4];
  #pragma unroll
  for (int i = 0; i < 4; ++i) {
    int ch = tid + i * 256;
    int r = ch >> 3, c = ch & 7;
    apx[i]  = V + (size_t)(m0 + r) * Dd + c * 4;
    asts[i] = (uint32_t)(r * ROWB + c * 8);
  }

  auto lda = [&](int it, float4 pf[4]) {
    const int k0 = it * 32;
    #pragma unroll
    for (int i = 0; i < 4; ++i)
      pf[i] = *reinterpret_cast<const float4*>(apx[i] + k0);
  };
  auto sta = [&](const float4 pf[4], int s) {
    const uint32_t base = sb + (uint32_t)s * V_STAGE;
    #pragma unroll
    for (int i = 0; i < 4; ++i)
      sts64(base + asts[i], f2h2(pf[i].x, pf[i].y), f2h2(pf[i].z, pf[i].w));
  };
  auto ldb = [&](int it, int s) {
    const int k0 = it * 32;
    const uint32_t base = sb + (uint32_t)s * V_STAGE + V_AREG;
    #pragma unroll
    for (int i = 0; i < 2; ++i) {
      int ch = tid + i * 256;                 // 512 chunks: 128 rows x 4
      int r = ch >> 2, c = ch & 3;
      cp16(base + (uint32_t)(r * ROWB + c * 16),
           g_WvT + (size_t)(n0 + r) * Dd + k0 + c * 8);
    }
    cp_commit();
  };

  float cc[4][4][4];
  #pragma unroll
  for (int i = 0; i < 4; ++i)
    #pragma unroll
    for (int j = 0; j < 4; ++j)
      #pragma unroll
      for (int t = 0; t < 4; ++t) cc[i][j][t] = 0.f;

  const int NIT = Dd / 32;   // 64
  float4 pf[4];
  lda(0, pf);
  sta(pf, 0);
  ldb(0, 0);
  lda(1, pf);

  for (int it = 0; it < NIT; ++it) {
    const int s = it & 1;
    if (it + 1 < NIT) {
      sta(pf, s ^ 1);
      ldb(it + 1, s ^ 1);
    } else cp_commit();
    cp_wait1();
    __syncthreads();
    if (it + 2 < NIT) lda(it + 2, pf);

    const __half* As = reinterpret_cast<const __half*>(smem + (size_t)s * V_STAGE);
    const __half* Bs = As + 128 * ROWH;

    #pragma unroll
    for (int ks = 0; ks < 2; ++ks) {
      const int kc = ks * 16;
      uint32_t a[4][4];
      #pragma unroll
      for (int i = 0; i < 4; ++i) {
        const int r = wm * 64 + i * 16 + g;
        a[i][0] = ldh2(As + (r    ) * ROWH + kc + 2 * tig);
        a[i][1] = ldh2(As + (r + 8) * ROWH + kc + 2 * tig);
        a[i][2] = ldh2(As + (r    ) * ROWH + kc + 2 * tig + 8);
        a[i][3] = ldh2(As + (r + 8) * ROWH + kc + 2 * tig + 8);
      }
      uint32_t b[4][2];
      #pragma unroll
      for (int j = 0; j < 4; ++j) {
        const int n = wn * 32 + j * 8 + g;
        b[j][0] = ldh2(Bs + n * ROWH + kc + 2 * tig);
        b[j][1] = ldh2(Bs + n * ROWH + kc + 2 * tig + 8);
      }
      #pragma unroll
      for (int i = 0; i < 4; ++i)
        #pragma unroll
        for (int j = 0; j < 4; ++j)
          mma16(cc[i][j], a[i], b[j]);
    }
    __syncthreads();
  }

  // Epilogue: out[r, n] = coef[r] * (acc + bv[n])
  float bvc[4][2];
  #pragma unroll
  for (int j = 0; j < 4; ++j) {
    const int col = n0 + wn * 32 + j * 8 + 2 * tig;
    bvc[j][0] = bv[col]; bvc[j][1] = bv[col + 1];
  }
  #pragma unroll
  for (int i = 0; i < 4; ++i) {
    const int r0 = m0 + wm * 64 + i * 16 + g;
    const int r1 = r0 + 8;
    const float c0 = g_qk[r0] / (g_sQ[r0] * g_sK[r0] + 1e-6f);
    const float c1 = g_qk[r1] / (g_sQ[r1] * g_sK[r1] + 1e-6f);
    #pragma unroll
    for (int j = 0; j < 4; ++j) {
      const int col = n0 + wn * 32 + j * 8 + 2 * tig;
      float2 v0, v1;
      v0.x = c0 * (cc[i][j][0] + bvc[j][0]);
      v0.y = c0 * (cc[i][j][1] + bvc[j][1]);
      v1.x = c1 * (cc[i][j][2] + bvc[j][0]);
      v1.y = c1 * (cc[i][j][3] + bvc[j][1]);
      *reinterpret_cast<float2*>(out + (size_t)r0 * Dd + col) = v0;
      *reinterpret_cast<float2*>(out + (size_t)r1 * Dd + col) = v1;
    }
  }
}

// ---------------- host launcher ----------------
extern "C" void kernel_launch(void* const* d_in, const int* /*in_sizes*/, int /*n_in*/,
                              void* d_out, int /*out_size*/) {
  const float* Q  = (const float*)d_in[0];
  const float* K  = (const float*)d_in[1];
  const float* V  = (const float*)d_in[2];
  const float* Wq = (const float*)d_in[3];
  const float* bq = (const float*)d_in[4];
  const float* Wk = (const float*)d_in[5];
  const float* bk = (const float*)d_in[6];
  const float* Wv = (const float*)d_in[7];
  const float* bv = (const float*)d_in[8];
  float* out = (float*)d_out;

  cudaFuncSetAttribute(gemm_qk_kernel, cudaFuncAttributeMaxDynamicSharedMemorySize, QK_SMEM);
  cudaFuncSetAttribute(gemm_v_kernel,  cudaFuncAttributeMaxDynamicSharedMemorySize, V_SMEM);

  // launch index 3 is the one ncu profiles -> gemm_qk there
  transpose_qk_kernel<<<dim3(Ff / 32, Dd / 32, 2), dim3(32, 8)>>>(Wq, Wk);   // 0
  transpose_v_kernel <<<dim3(Dd / 32, Dd / 32),    dim3(32, 8)>>>(Wv);        // 1
  zero_kernel<<<Bn / 256, 256>>>();                                           // 2
  gemm_qk_kernel<<<dim3(Ff / 128, Bn / 64), 256, QK_SMEM>>>(Q, K, bq, bk);    // 3
  gemm_v_kernel <<<dim3(Dd / 128, Bn / 128), 256, V_SMEM>>>(V, bv, out);      // 4
}

// round 7
// speedup vs baseline: 1.6037x; 1.1004x over previous
#include <cuda_runtime.h>
#include <cuda_fp16.h>
#include <cstdint>
#include <cstddef>

#define DEV __device__ __forceinline__

static constexpr int Bn = 8192;   // batch rows
static constexpr int Dd = 2048;   // model dim (K of GEMMs, N of V GEMM)
static constexpr int Ff = 1024;   // feature dim (N of Q/K GEMMs)

// ---------------- scratch (device globals: allocation-free) ----------------
__device__ __half g_Qh [(size_t)Bn * Dd];   // 32 MB
__device__ __half g_Kh [(size_t)Bn * Dd];   // 32 MB
__device__ __half g_Vh [(size_t)Bn * Dd];   // 32 MB
__device__ __half g_WqT[(size_t)Ff * Dd];   // [F][D] 4 MB
__device__ __half g_WkT[(size_t)Ff * Dd];   // [F][D] 4 MB
__device__ __half g_WvT[(size_t)Dd * Dd];   // [D][D] 8 MB
__device__ float g_sQ[Bn];
__device__ float g_sK[Bn];
__device__ float g_qk[Bn];

// ---------------- helpers ----------------
DEV uint32_t smem_u32(const void* p) {
  uint32_t a;
  asm("{ .reg .u64 t; cvta.to.shared.u64 t, %1; cvt.u32.u64 %0, t; }" : "=r"(a) : "l"(p));
  return a;
}
DEV void cp16(uint32_t dst, const void* src) {
  asm volatile("cp.async.cg.shared.global [%0], [%1], 16;" :: "r"(dst), "l"(src));
}
DEV void cp_commit() { asm volatile("cp.async.commit_group;" ::: "memory"); }
DEV void cp_wait1()  { asm volatile("cp.async.wait_group 1;" ::: "memory"); }
DEV void cp_wait2()  { asm volatile("cp.async.wait_group 2;" ::: "memory"); }

// mma m16n8k16 fp16 (fp32 acc): A row-major (4 regs = 8 halves), B col-major (2 regs)
DEV void mma16(float c[4], const uint32_t a[4], const uint32_t b[2]) {
  asm volatile(
    "mma.sync.aligned.m16n8k16.row.col.f32.f16.f16.f32 "
    "{%0,%1,%2,%3}, {%4,%5,%6,%7}, {%8,%9}, {%0,%1,%2,%3};"
    : "+f"(c[0]), "+f"(c[1]), "+f"(c[2]), "+f"(c[3])
    : "r"(a[0]), "r"(a[1]), "r"(a[2]), "r"(a[3]), "r"(b[0]), "r"(b[1]));
}

DEV float elu_f(float x) { return x > 0.f ? x : expm1f(x); }
DEV uint32_t ldh2(const __half* p) { return *reinterpret_cast<const uint32_t*>(p); }
DEV uint32_t f2h2(float x, float y) {
  __half2 h = __floats2half2_rn(x, y);
  return *reinterpret_cast<uint32_t*>(&h);
}

// Smem rows: 64 k-halves (128 B data) padded to 72 halves (144 B = 9*16 B).
// byte addr = 144r + 4*tig (+16c) -> bank (4r + tig + 4c) mod 32: conflict-free
// for both A-frag and B-frag access patterns.
static constexpr int ROWH   = 72;                  // halves per padded row
static constexpr int ROWB   = 144;                 // bytes per padded row

// ---------------- prep kernels ----------------
// One kernel converts all three activations: 8 floats / thread, 16-B fp16 store.
__global__ void f2h_all_kernel(const float* __restrict__ Q,
                               const float* __restrict__ K,
                               const float* __restrict__ V) {
  const int bi = blockIdx.x;            // 0..24575 (8192 blocks per tensor)
  const int which = bi >> 13;
  const int blk = bi & 8191;
  const float* src = (which == 0) ? Q : (which == 1) ? K : V;
  __half* dst = (which == 0) ? g_Qh : (which == 1) ? g_Kh : g_Vh;
  const size_t base = ((size_t)blk * 256 + threadIdx.x) * 8;
  float4 a = *reinterpret_cast<const float4*>(src + base);
  float4 b = *reinterpret_cast<const float4*>(src + base + 4);
  uint4 o;
  o.x = f2h2(a.x, a.y); o.y = f2h2(a.z, a.w);
  o.z = f2h2(b.x, b.y); o.w = f2h2(b.z, b.w);
  *reinterpret_cast<uint4*>(dst + base) = o;
}

__global__ void transpose_all_kernel(const float* __restrict__ Wq,
                                     const float* __restrict__ Wk,
                                     const float* __restrict__ Wv) {
  // src[R=2048][C] fp32 -> dst[C][R=2048] fp16;  z selects tensor
  __shared__ float tile[32][33];
  const int z = blockIdx.z;
  if (z < 2 && blockIdx.x >= Ff / 32) return;
  const float* src = (z == 0) ? Wq : (z == 1) ? Wk : Wv;
  __half* dst = (z == 0) ? g_WqT : (z == 1) ? g_WkT : g_WvT;
  const int C = (z == 2) ? Dd : Ff;
  const int c0 = blockIdx.x * 32, r0 = blockIdx.y * 32;
  const int tx = threadIdx.x, ty = threadIdx.y;
  #pragma unroll
  for (int i = 0; i < 32; i += 8)
    tile[ty + i][tx] = src[(size_t)(r0 + ty + i) * C + (c0 + tx)];
  __syncthreads();
  #pragma unroll
  for (int i = 0; i < 32; i += 8)
    dst[(size_t)(c0 + ty + i) * Dd + (r0 + tx)] = __float2half_rn(tile[tx][ty + i]);
}

__global__ void zero_kernel() {
  int i = blockIdx.x * blockDim.x + threadIdx.x;
  if (i < Bn) { g_sQ[i] = 0.f; g_sK[i] = 0.f; g_qk[i] = 0.f; }
}

// ---------------- fused Q/K feature kernel ----------------
// CTA 64 rows x 128 feature cols, BOTH gemms; 8 warps (wm 2 x wn 4),
// warp tile 32x32 per gemm. K-chunk 64 halves, 2-stage cp.async, 2 CTAs/SM.
// Stage layout (halves): A region 128 rows (AQ 64 | AK 64) then
// B region 256 rows (BQ 128 | BK 128). Stage = 55296 B.
static constexpr int QK_STAGE = (128 + 256) * ROWB;       // 55296
static constexpr int QK_SMEM  = 2 * QK_STAGE;             // 110592

__global__ void __launch_bounds__(256, 2)
gemm_qk_kernel(const float* __restrict__ bq, const float* __restrict__ bk)
{
  extern __shared__ __align__(128) char smem[];
  __half* fs = reinterpret_cast<__half*>(smem);
  const uint32_t sb = smem_u32(smem);
  const int tid = threadIdx.x;
  const int wid = tid >> 5, lane = tid & 31;
  const int g = lane >> 2, tig = lane & 3;
  const int wm = wid >> 2, wn = wid & 3;
  const int m0 = blockIdx.y * 64;
  const int n0 = blockIdx.x * 128;

  auto load_stage = [&](int it, int s) {
    const int k0 = it * 64;                 // halves
    const uint32_t base = sb + (uint32_t)s * QK_STAGE;
    // A region: 1024 16B chunks (rows 0-63 Q, 64-127 K); 4 per thread.
    #pragma unroll
    for (int i = 0; i < 4; ++i) {
      int ch = tid + i * 256;               // i<2 -> Q, i>=2 -> K (uniform)
      int r = ch >> 3, c = ch & 7;
      uint32_t off = (uint32_t)(r * ROWB + c * 16);
      const __half* src = (i < 2) ? (g_Qh + (size_t)(m0 + r) * Dd)
                                  : (g_Kh + (size_t)(m0 + r - 64) * Dd);
      cp16(base + off, src + k0 + c * 8);
    }
    // B region: 2048 chunks (rows 0-127 Wq, 128-255 Wk); 8 per thread.
    #pragma unroll
    for (int i = 0; i < 8; ++i) {
      int ch = tid + i * 256;               // i<4 -> BQ, i>=4 -> BK (uniform)
      int r = ch >> 3, c = ch & 7;
      uint32_t off = (uint32_t)(128 * ROWB + r * ROWB + c * 16);
      const __half* src = (i < 4) ? (g_WqT + (size_t)(n0 + r) * Dd)
                                  : (g_WkT + (size_t)(n0 + r - 128) * Dd);
      cp16(base + off, src + k0 + c * 8);
    }
    cp_commit();
  };

  float cQ[2][4][4], cK[2][4][4];
  #pragma unroll
  for (int i = 0; i < 2; ++i)
    #pragma unroll
    for (int j = 0; j < 4; ++j)
      #pragma unroll
      for (int t = 0; t < 4; ++t) { cQ[i][j][t] = 0.f; cK[i][j][t] = 0.f; }

  load_stage(0, 0);

  const int NIT = Dd / 64;   // 32
  for (int it = 0; it < NIT; ++it) {
    __syncthreads();
    if (it + 1 < NIT) load_stage(it + 1, (it + 1) & 1);
    else cp_commit();
    cp_wait1();
    __syncthreads();

    const __half* AQs = fs + (size_t)(it & 1) * (QK_STAGE / 2);
    const __half* AKs = AQs + 64 * ROWH;
    const __half* BQs = AQs + 128 * ROWH;
    const __half* BKs = BQs + 128 * ROWH;

    #pragma unroll
    for (int ks = 0; ks < 4; ++ks) {
      const int kc = ks * 16;
      uint32_t aQ[2][4], aK[2][4];
      #pragma unroll
      for (int i = 0; i < 2; ++i) {
        const int r = wm * 32 + i * 16 + g;
        aQ[i][0] = ldh2(AQs + (r    ) * ROWH + kc + 2 * tig);
        aQ[i][1] = ldh2(AQs + (r + 8) * ROWH + kc + 2 * tig);
        aQ[i][2] = ldh2(AQs + (r    ) * ROWH + kc + 2 * tig + 8);
        aQ[i][3] = ldh2(AQs + (r + 8) * ROWH + kc + 2 * tig + 8);
        aK[i][0] = ldh2(AKs + (r    ) * ROWH + kc + 2 * tig);
        aK[i][1] = ldh2(AKs + (r + 8) * ROWH + kc + 2 * tig);
        aK[i][2] = ldh2(AKs + (r    ) * ROWH + kc + 2 * tig + 8);
        aK[i][3] = ldh2(AKs + (r + 8) * ROWH + kc + 2 * tig + 8);
      }
      uint32_t bQ[4][2], bK[4][2];
      #pragma unroll
      for (int j = 0; j < 4; ++j) {
        const int n = wn * 32 + j * 8 + g;
        bQ[j][0] = ldh2(BQs + n * ROWH + kc + 2 * tig);
        bQ[j][1] = ldh2(BQs + n * ROWH + kc + 2 * tig + 8);
        bK[j][0] = ldh2(BKs + n * ROWH + kc + 2 * tig);
        bK[j][1] = ldh2(BKs + n * ROWH + kc + 2 * tig + 8);
      }
      #pragma unroll
      for (int i = 0; i < 2; ++i)
        #pragma unroll
        for (int j = 0; j < 4; ++j) {
          mma16(cQ[i][j], aQ[i], bQ[j]);
          mma16(cK[i][j], aK[i], bK[j]);
        }
    }
  }

  // Epilogue: bias + ELU + per-row reductions (sum Q, sum K, sum Q*K)
  float bqc[4][2], bkc[4][2];
  #pragma unroll
  for (int j = 0; j < 4; ++j) {
    const int col = n0 + wn * 32 + j * 8 + 2 * tig;
    bqc[j][0] = bq[col]; bqc[j][1] = bq[col + 1];
    bkc[j][0] = bk[col]; bkc[j][1] = bk[col + 1];
  }
  #pragma unroll
  for (int i = 0; i < 2; ++i) {
    const int r0 = m0 + wm * 32 + i * 16 + g;
    const int r1 = r0 + 8;
    float s0q = 0.f, s0k = 0.f, p0 = 0.f, s1q = 0.f, s1k = 0.f, p1 = 0.f;
    #pragma unroll
    for (int j = 0; j < 4; ++j) {
      float q00 = elu_f(cQ[i][j][0] + bqc[j][0]);
      float q01 = elu_f(cQ[i][j][1] + bqc[j][1]);
      float q10 = elu_f(cQ[i][j][2] + bqc[j][0]);
      float q11 = elu_f(cQ[i][j][3] + bqc[j][1]);
      float k00 = elu_f(cK[i][j][0] + bkc[j][0]);
      float k01 = elu_f(cK[i][j][1] + bkc[j][1]);
      float k10 = elu_f(cK[i][j][2] + bkc[j][0]);
      float k11 = elu_f(cK[i][j][3] + bkc[j][1]);
      s0q += q00 + q01; s0k += k00 + k01; p0 += q00 * k00 + q01 * k01;
      s1q += q10 + q11; s1k += k10 + k11; p1 += q10 * k10 + q11 * k11;
    }
    #pragma unroll
    for (int m = 1; m <= 2; m <<= 1) {
      s0q += __shfl_xor_sync(0xffffffffu, s0q, m);
      s0k += __shfl_xor_sync(0xffffffffu, s0k, m);
      p0  += __shfl_xor_sync(0xffffffffu, p0,  m);
      s1q += __shfl_xor_sync(0xffffffffu, s1q, m);
      s1k += __shfl_xor_sync(0xffffffffu, s1k, m);
      p1  += __shfl_xor_sync(0xffffffffu, p1,  m);
    }
    if (tig == 0) {
      atomicAdd(&g_sQ[r0], s0q); atomicAdd(&g_sK[r0], s0k); atomicAdd(&g_qk[r0], p0);
      atomicAdd(&g_sQ[r1], s1q); atomicAdd(&g_sK[r1], s1k); atomicAdd(&g_qk[r1], p1);
    }
  }
}

// ---------------- V projection kernel ----------------
// CTA 128x128, K-chunk 64, 3-stage pipeline (A | B per stage), 2 CTAs/SM.
static constexpr int TILE_B  = 128 * ROWB;                // 18432
static constexpr int V_STAGE = 2 * TILE_B;                // 36864
static constexpr int V_SMEM  = 3 * V_STAGE;               // 110592

__global__ void __launch_bounds__(256, 2)
gemm_v_kernel(const float* __restrict__ bv, float* __restrict__ out)
{
  extern __shared__ __align__(128) char smem[];
  __half* fs = reinterpret_cast<__half*>(smem);
  const uint32_t sb = smem_u32(smem);
  const int tid = threadIdx.x;
  const int wid = tid >> 5, lane = tid & 31;
  const int g = lane >> 2, tig = lane & 3;
  const int wm = wid >> 2, wn = wid & 3;
  const int m0 = blockIdx.y * 128;
  const int n0 = blockIdx.x * 128;

  auto load_stage = [&](int it, int s) {
    const int k0 = it * 64;
    const uint32_t base = sb + (uint32_t)s * V_STAGE;
    #pragma unroll
    for (int i = 0; i < 4; ++i) {
      int ch = tid + i * 256;
      int r = ch >> 3, c = ch & 7;
      uint32_t off = (uint32_t)(r * ROWB + c * 16);
      cp16(base + off,          g_Vh  + (size_t)(m0 + r) * Dd + k0 + c * 8);
      cp16(base + TILE_B + off, g_WvT + (size_t)(n0 + r) * Dd + k0 + c * 8);
    }
    cp_commit();
  };

  float cc[4][4][4];
  #pragma unroll
  for (int i = 0; i < 4; ++i)
    #pragma unroll
    for (int j = 0; j < 4; ++j)
      #pragma unroll
      for (int t = 0; t < 4; ++t) cc[i][j][t] = 0.f;

  load_stage(0, 0);
  load_stage(1, 1);

  const int NIT = Dd / 64;   // 32
  for (int it = 0; it < NIT; ++it) {
    __syncthreads();
    if (it + 2 < NIT) load_stage(it + 2, (it + 2) % 3);
    else cp_commit();
    cp_wait2();
    __syncthreads();

    const __half* As = fs + (size_t)(it % 3) * (V_STAGE / 2);
    const __half* Bs = As + TILE_B / 2;

    #pragma unroll
    for (int ks = 0; ks < 4; ++ks) {
      const int kc = ks * 16;
      uint32_t a[4][4];
      #pragma unroll
      for (int i = 0; i < 4; ++i) {
        const int r = wm * 64 + i * 16 + g;
        a[i][0] = ldh2(As + (r    ) * ROWH + kc + 2 * tig);
        a[i][1] = ldh2(As + (r + 8) * ROWH + kc + 2 * tig);
        a[i][2] = ldh2(As + (r    ) * ROWH + kc + 2 * tig + 8);
        a[i][3] = ldh2(As + (r + 8) * ROWH + kc + 2 * tig + 8);
      }
      uint32_t b[4][2];
      #pragma unroll
      for (int j = 0; j < 4; ++j) {
        const int n = wn * 32 + j * 8 + g;
        b[j][0] = ldh2(Bs + n * ROWH + kc + 2 * tig);
        b[j][1] = ldh2(Bs + n * ROWH + kc + 2 * tig + 8);
      }
      #pragma unroll
      for (int i = 0; i < 4; ++i)
        #pragma unroll
        for (int j = 0; j < 4; ++j)
          mma16(cc[i][j], a[i], b[j]);
    }
  }

  // Epilogue: out[r, n] = coef[r] * (acc + bv[n])
  float bvc[4][2];
  #pragma unroll
  for (int j = 0; j < 4; ++j) {
    const int col = n0 + wn * 32 + j * 8 + 2 * tig;
    bvc[j][0] = bv[col]; bvc[j][1] = bv[col + 1];
  }
  #pragma unroll
  for (int i = 0; i < 4; ++i) {
    const int r0 = m0 + wm * 64 + i * 16 + g;
    const int r1 = r0 + 8;
    const float c0 = g_qk[r0] / (g_sQ[r0] * g_sK[r0] + 1e-6f);
    const float c1 = g_qk[r1] / (g_sQ[r1] * g_sK[r1] + 1e-6f);
    #pragma unroll
    for (int j = 0; j < 4; ++j) {
      const int col = n0 + wn * 32 + j * 8 + 2 * tig;
      float2 v0, v1;
      v0.x = c0 * (cc[i][j][0] + bvc[j][0]);
      v0.y = c0 * (cc[i][j][1] + bvc[j][1]);
      v1.x = c1 * (cc[i][j][2] + bvc[j][0]);
      v1.y = c1 * (cc[i][j][3] + bvc[j][1]);
      *reinterpret_cast<float2*>(out + (size_t)r0 * Dd + col) = v0;
      *reinterpret_cast<float2*>(out + (size_t)r1 * Dd + col) = v1;
    }
  }
}

// ---------------- host launcher ----------------
extern "C" void kernel_launch(void* const* d_in, const int* /*in_sizes*/, int /*n_in*/,
                              void* d_out, int /*out_size*/) {
  const float* Q  = (const float*)d_in[0];
  const float* K  = (const float*)d_in[1];
  const float* V  = (const float*)d_in[2];
  const float* Wq = (const float*)d_in[3];
  const float* bq = (const float*)d_in[4];
  const float* Wk = (const float*)d_in[5];
  const float* bk = (const float*)d_in[6];
  const float* Wv = (const float*)d_in[7];
  const float* bv = (const float*)d_in[8];
  float* out = (float*)d_out;

  cudaFuncSetAttribute(gemm_qk_kernel, cudaFuncAttributeMaxDynamicSharedMemorySize, QK_SMEM);
  cudaFuncSetAttribute(gemm_v_kernel,  cudaFuncAttributeMaxDynamicSharedMemorySize, V_SMEM);

  // index 3 (the launch ncu profiles) = gemm_qk
  f2h_all_kernel<<<3 * 8192, 256>>>(Q, K, V);                                 // 0
  transpose_all_kernel<<<dim3(Dd / 32, Dd / 32, 3), dim3(32, 8)>>>(Wq, Wk, Wv); // 1
  zero_kernel<<<Bn / 256, 256>>>();                                           // 2
  gemm_qk_kernel<<<dim3(Ff / 128, Bn / 64), 256, QK_SMEM>>>(bq, bk);          // 3
  gemm_v_kernel <<<dim3(Dd / 128, Bn / 128), 256, V_SMEM>>>(bv, out);         // 4
}